// round 12
// baseline (speedup 1.0000x reference)
#include <cuda_runtime.h>
#include <cuda_bf16.h>
#include <math.h>
#include <stdint.h>

#define HIDDEN 3072
#define SEQ 2048
#define NH 24
#define HD 128
#define MLPD 12288
#define W1N 21504   // 3*HIDDEN + MLPD
#define CATN 15360  // HIDDEN + MLPD
#define MODN 9216   // 3*HIDDEN

// ---------------- scratch (device globals; no allocations allowed) ----------
__device__ float d_mod[MODN];
__device__ float d_xmod[(size_t)SEQ * HIDDEN];
__device__ float d_h[(size_t)SEQ * W1N];
__device__ float d_v[(size_t)NH * SEQ * HD];
__device__ float d_s[(size_t)NH * SEQ * SEQ];
// bf16 split operands (16B aligned for vector access)
__device__ __align__(16) __nv_bfloat16 d_a1h[(size_t)SEQ * HIDDEN];
__device__ __align__(16) __nv_bfloat16 d_a1l[(size_t)SEQ * HIDDEN];
__device__ __align__(16) __nv_bfloat16 d_a2h[(size_t)SEQ * CATN];
__device__ __align__(16) __nv_bfloat16 d_a2l[(size_t)SEQ * CATN];
__device__ __align__(16) __nv_bfloat16 d_w1th[(size_t)W1N * HIDDEN];  // [N=W1N, K=HIDDEN]
__device__ __align__(16) __nv_bfloat16 d_w1tl[(size_t)W1N * HIDDEN];
__device__ __align__(16) __nv_bfloat16 d_w2th[(size_t)HIDDEN * CATN]; // [N=HIDDEN, K=CATN]
__device__ __align__(16) __nv_bfloat16 d_w2tl[(size_t)HIDDEN * CATN];
// attention bf16 split operands
__device__ __align__(16) __nv_bfloat16 d_qh[(size_t)NH * SEQ * HD];
__device__ __align__(16) __nv_bfloat16 d_ql[(size_t)NH * SEQ * HD];
__device__ __align__(16) __nv_bfloat16 d_kh[(size_t)NH * SEQ * HD];
__device__ __align__(16) __nv_bfloat16 d_kl[(size_t)NH * SEQ * HD];
__device__ __align__(16) __nv_bfloat16 d_vth[(size_t)NH * HD * SEQ];
__device__ __align__(16) __nv_bfloat16 d_vtl[(size_t)NH * HD * SEQ];
__device__ __align__(16) __nv_bfloat16 d_sh[(size_t)NH * SEQ * SEQ];
__device__ __align__(16) __nv_bfloat16 d_sl[(size_t)NH * SEQ * SEQ];

// =================== helpers ================================================
__device__ __forceinline__ uint32_t smem_u32(const void* p) {
    uint32_t a;
    asm("{ .reg .u64 t; cvta.to.shared.u64 t, %1; cvt.u32.u64 %0, t; }" : "=r"(a) : "l"(p));
    return a;
}
__device__ __forceinline__ void cp_async16(void* sdst, const void* gsrc) {
    asm volatile("cp.async.cg.shared.global [%0], [%1], 16;"
                 :: "r"(smem_u32(sdst)), "l"(gsrc) : "memory");
}
__device__ __forceinline__ void mma16816(float* d, const uint32_t* a, const uint32_t* b) {
    asm volatile(
        "mma.sync.aligned.m16n8k16.row.col.f32.bf16.bf16.f32 "
        "{%0,%1,%2,%3}, {%4,%5,%6,%7}, {%8,%9}, {%0,%1,%2,%3};"
        : "+f"(d[0]), "+f"(d[1]), "+f"(d[2]), "+f"(d[3])
        : "r"(a[0]), "r"(a[1]), "r"(a[2]), "r"(a[3]), "r"(b[0]), "r"(b[1]));
}

// =================== HMMA GEMM: C[M,N] = A[M,K] @ B^T (B:[N,K]) =============
// bf16 split-3: Ah*Bh + Al*Bh + Ah*Bl, fp32 accumulate. Double-buffered cp.async.
// Template NT = n-subtiles per warp (8-col each). CTA tile = 128 x (NT*32).
// warp layout 2 (M) x 4 (N); warp tile 64 x NT*8.
// mode 0: C = alpha*acc
// mode 1: C = acc + bias
// mode 2: C = resid + gate*(acc + bias)
// mode 3: split(acc) -> outH/outL bf16
#define KC 32
#define TSTR 40                      // padded k-stride; 80B rows, 16B aligned
#define ATILE (128 * TSTR)           // per-operand A tile elems
template <int NT>
__global__ void __launch_bounds__(256, (NT == 4) ? 2 : 1) hmma_gemm_kernel(
    const __nv_bfloat16* __restrict__ Ah, const __nv_bfloat16* __restrict__ Al, long long sA,
    const __nv_bfloat16* __restrict__ Bh, const __nv_bfloat16* __restrict__ Bl, long long sB,
    float* __restrict__ C, int ldc, long long sC,
    int K, float alpha, int mode,
    const float* __restrict__ bias,
    const float* __restrict__ resid,
    const float* __restrict__ gate,
    __nv_bfloat16* __restrict__ outH,
    __nv_bfloat16* __restrict__ outL) {
    constexpr int BN = NT * 32;
    constexpr int BTILE = BN * TSTR;
    constexpr int STAGE = 2 * ATILE + 2 * BTILE;
    extern __shared__ __align__(16) __nv_bfloat16 smem[];

    const long long bz = blockIdx.z;
    Ah += bz * sA; Al += bz * sA;
    Bh += bz * sB; Bl += bz * sB;

    const int tid = threadIdx.x;
    const int wid = tid >> 5, lane = tid & 31;
    const int m0 = blockIdx.x * 128, n0 = blockIdx.y * BN;
    const int wm = (wid >> 2) * 64, wn = (wid & 3) * (NT * 8);

    float acc[4][NT][4];
#pragma unroll
    for (int mt = 0; mt < 4; mt++)
#pragma unroll
        for (int nt = 0; nt < NT; nt++)
#pragma unroll
            for (int r = 0; r < 4; r++) acc[mt][nt][r] = 0.0f;

    const int nk = K / KC;

    // loader lambda-ish macro: fill stage s with K-chunk kc
#define LOAD_STAGE(SB, KCOFF)                                                        \
    {                                                                                \
        _Pragma("unroll")                                                            \
        for (int c = tid; c < 512; c += 256) {                                       \
            int row = c >> 2, off = (c & 3) * 8;                                     \
            int so = row * TSTR + off;                                               \
            cp_async16((SB) + so,         Ah + (size_t)(m0 + row) * K + (KCOFF) + off); \
            cp_async16((SB) + ATILE + so, Al + (size_t)(m0 + row) * K + (KCOFF) + off); \
        }                                                                            \
        _Pragma("unroll")                                                            \
        for (int c = tid; c < BN * 4; c += 256) {                                    \
            int row = c >> 2, off = (c & 3) * 8;                                     \
            int so = row * TSTR + off;                                               \
            cp_async16((SB) + 2 * ATILE + so,         Bh + (size_t)(n0 + row) * K + (KCOFF) + off); \
            cp_async16((SB) + 2 * ATILE + BTILE + so, Bl + (size_t)(n0 + row) * K + (KCOFF) + off); \
        }                                                                            \
        asm volatile("cp.async.commit_group;" ::: "memory");                         \
    }

    LOAD_STAGE(smem, 0)

    for (int it = 0; it < nk; it++) {
        asm volatile("cp.async.wait_group 0;" ::: "memory");
        __syncthreads();
        if (it + 1 < nk) {
            __nv_bfloat16* sb = smem + ((it + 1) & 1) * STAGE;
            LOAD_STAGE(sb, (it + 1) * KC)
        }
        const __nv_bfloat16* sAh = smem + (it & 1) * STAGE;
        const __nv_bfloat16* sAl = sAh + ATILE;
        const __nv_bfloat16* sBh = sAh + 2 * ATILE;
        const __nv_bfloat16* sBl = sAh + 2 * ATILE + BTILE;

#pragma unroll
        for (int ks = 0; ks < 2; ks++) {
            const int k0 = ks * 16;
            const int ar = lane >> 2, ak = (lane & 3) * 2;
            uint32_t ah[4][4], bh[NT][2], xl[4][4];
#pragma unroll
            for (int mt = 0; mt < 4; mt++) {
                int base = (wm + mt * 16 + ar) * TSTR + k0 + ak;
                ah[mt][0] = *(const uint32_t*)&sAh[base];
                ah[mt][1] = *(const uint32_t*)&sAh[base + 8 * TSTR];
                ah[mt][2] = *(const uint32_t*)&sAh[base + 8];
                ah[mt][3] = *(const uint32_t*)&sAh[base + 8 * TSTR + 8];
            }
#pragma unroll
            for (int nt = 0; nt < NT; nt++) {
                int base = (wn + nt * 8 + ar) * TSTR + k0 + ak;
                bh[nt][0] = *(const uint32_t*)&sBh[base];
                bh[nt][1] = *(const uint32_t*)&sBh[base + 8];
            }
#pragma unroll
            for (int mt = 0; mt < 4; mt++)
#pragma unroll
                for (int nt = 0; nt < NT; nt++) mma16816(acc[mt][nt], ah[mt], bh[nt]);
#pragma unroll
            for (int mt = 0; mt < 4; mt++) {
                int base = (wm + mt * 16 + ar) * TSTR + k0 + ak;
                xl[mt][0] = *(const uint32_t*)&sAl[base];
                xl[mt][1] = *(const uint32_t*)&sAl[base + 8 * TSTR];
                xl[mt][2] = *(const uint32_t*)&sAl[base + 8];
                xl[mt][3] = *(const uint32_t*)&sAl[base + 8 * TSTR + 8];
            }
#pragma unroll
            for (int mt = 0; mt < 4; mt++)
#pragma unroll
                for (int nt = 0; nt < NT; nt++) mma16816(acc[mt][nt], xl[mt], bh[nt]);
            uint32_t bl[NT][2];
#pragma unroll
            for (int nt = 0; nt < NT; nt++) {
                int base = (wn + nt * 8 + ar) * TSTR + k0 + ak;
                bl[nt][0] = *(const uint32_t*)&sBl[base];
                bl[nt][1] = *(const uint32_t*)&sBl[base + 8];
            }
#pragma unroll
            for (int mt = 0; mt < 4; mt++)
#pragma unroll
                for (int nt = 0; nt < NT; nt++) mma16816(acc[mt][nt], ah[mt], bl[nt]);
        }
    }
#undef LOAD_STAGE

    // epilogue
#pragma unroll
    for (int mt = 0; mt < 4; mt++) {
#pragma unroll
        for (int h = 0; h < 2; h++) {
            long long m = (long long)m0 + wm + mt * 16 + (lane >> 2) + h * 8;
            long long crow = bz * sC + m * ldc;
#pragma unroll
            for (int nt = 0; nt < NT; nt++) {
                int n = n0 + wn + nt * 8 + (lane & 3) * 2;
                float vx = acc[mt][nt][h * 2 + 0];
                float vy = acc[mt][nt][h * 2 + 1];
                if (mode == 0) {
                    vx *= alpha; vy *= alpha;
                    float2 o; o.x = vx; o.y = vy;
                    *(float2*)(C + crow + n) = o;
                } else if (mode == 3) {
                    __nv_bfloat162 hp, lp;
                    hp.x = __float2bfloat16(vx);
                    hp.y = __float2bfloat16(vy);
                    lp.x = __float2bfloat16(vx - __bfloat162float(hp.x));
                    lp.y = __float2bfloat16(vy - __bfloat162float(hp.y));
                    *(uint32_t*)(outH + crow + n) = *(uint32_t*)&hp;
                    *(uint32_t*)(outL + crow + n) = *(uint32_t*)&lp;
                } else {
                    vx += bias[n]; vy += bias[n + 1];
                    if (mode == 2) {
                        float2 xv = *(const float2*)(resid + m * ldc + n);
                        vx = fmaf(gate[n],     vx, xv.x);
                        vy = fmaf(gate[n + 1], vy, xv.y);
                    }
                    float2 o; o.x = vx; o.y = vy;
                    *(float2*)(C + crow + n) = o;
                }
            }
        }
    }
}

// =================== split / transpose prep kernels =========================
__global__ void split_kernel(const float* __restrict__ src,
                             __nv_bfloat16* __restrict__ dh,
                             __nv_bfloat16* __restrict__ dl) {
    size_t i = ((size_t)blockIdx.x * 256 + threadIdx.x) * 4;
    float4 v = *(const float4*)(src + i);
    __nv_bfloat162 hA, hB, lA, lB;
    hA.x = __float2bfloat16(v.x); hA.y = __float2bfloat16(v.y);
    hB.x = __float2bfloat16(v.z); hB.y = __float2bfloat16(v.w);
    lA.x = __float2bfloat16(v.x - __bfloat162float(hA.x));
    lA.y = __float2bfloat16(v.y - __bfloat162float(hA.y));
    lB.x = __float2bfloat16(v.z - __bfloat162float(hB.x));
    lB.y = __float2bfloat16(v.w - __bfloat162float(hB.y));
    uint2 uh, ul;
    uh.x = *(uint32_t*)&hA; uh.y = *(uint32_t*)&hB;
    ul.x = *(uint32_t*)&lA; ul.y = *(uint32_t*)&lB;
    *(uint2*)(dh + i) = uh;
    *(uint2*)(dl + i) = ul;
}

// src fp32 [R, Cc] -> dh/dl bf16 [Cc, R] (transposed, split)
__global__ void transpose_split_kernel(const float* __restrict__ src, int R, int Cc,
                                       __nv_bfloat16* __restrict__ dh,
                                       __nv_bfloat16* __restrict__ dl) {
    __shared__ float t[32][33];
    int c0 = blockIdx.x * 32, r0 = blockIdx.y * 32;
    int tx = threadIdx.x, ty = threadIdx.y;
#pragma unroll
    for (int i = 0; i < 4; i++)
        t[ty + 8 * i][tx] = src[(size_t)(r0 + ty + 8 * i) * Cc + c0 + tx];
    __syncthreads();
#pragma unroll
    for (int i = 0; i < 4; i++) {
        float v = t[tx][ty + 8 * i];
        __nv_bfloat16 h = __float2bfloat16(v);
        size_t o = (size_t)(c0 + ty + 8 * i) * R + r0 + tx;
        dh[o] = h;
        dl[o] = __float2bfloat16(v - __bfloat162float(h));
    }
}

// per-head: d_v [h][SEQ][HD] fp32 -> d_vt [h][HD][SEQ] bf16 split
__global__ void transpose_split_v_kernel() {
    __shared__ float t[32][33];
    int h = blockIdx.z;
    int c0 = blockIdx.x * 32;   // d
    int r0 = blockIdx.y * 32;   // seq
    int tx = threadIdx.x, ty = threadIdx.y;
    const float* src = d_v + (size_t)h * SEQ * HD;
#pragma unroll
    for (int i = 0; i < 4; i++)
        t[ty + 8 * i][tx] = src[(size_t)(r0 + ty + 8 * i) * HD + c0 + tx];
    __syncthreads();
    size_t base = (size_t)h * HD * SEQ;
#pragma unroll
    for (int i = 0; i < 4; i++) {
        float v = t[tx][ty + 8 * i];
        __nv_bfloat16 hh = __float2bfloat16(v);
        size_t o = base + (size_t)(c0 + ty + 8 * i) * SEQ + r0 + tx;
        d_vth[o] = hh;
        d_vtl[o] = __float2bfloat16(v - __bfloat162float(hh));
    }
}

// =================== small kernels =========================================
__global__ void mod_gemv_kernel(const float* __restrict__ vec,
                                const float* __restrict__ mod_w,
                                const float* __restrict__ mod_b,
                                float* __restrict__ mod) {
    __shared__ float sv[HIDDEN];
    for (int i = threadIdx.x; i < HIDDEN; i += 256) {
        float v = vec[i];
        sv[i] = v / (1.0f + expf(-v));
    }
    __syncthreads();
    int j = blockIdx.x * 256 + threadIdx.x;
    const float* wp = mod_w + j;
    float acc = 0.0f;
#pragma unroll 8
    for (int k = 0; k < HIDDEN; k++) acc = fmaf(sv[k], wp[(size_t)k * MODN], acc);
    mod[j] = acc + mod_b[j];
}

__global__ void ln_mod_kernel(const float* __restrict__ x) {
    int row = blockIdx.x;
    const float* xr = x + (size_t)row * HIDDEN;
    __shared__ float r1[256], r2[256];
    float s = 0.0f, s2 = 0.0f;
    for (int i = threadIdx.x; i < HIDDEN; i += 256) {
        float v = xr[i];
        s += v;
        s2 = fmaf(v, v, s2);
    }
    r1[threadIdx.x] = s; r2[threadIdx.x] = s2;
    __syncthreads();
    for (int o = 128; o > 0; o >>= 1) {
        if (threadIdx.x < o) { r1[threadIdx.x] += r1[threadIdx.x + o]; r2[threadIdx.x] += r2[threadIdx.x + o]; }
        __syncthreads();
    }
    float mu  = r1[0] * (1.0f / HIDDEN);
    float var = r2[0] * (1.0f / HIDDEN) - mu * mu;
    float inv = rsqrtf(var + 1e-6f);
    float* orow = d_xmod + (size_t)row * HIDDEN;
    for (int i = threadIdx.x; i < HIDDEN; i += 256) {
        float sc = 1.0f + d_mod[HIDDEN + i];
        orow[i] = (xr[i] - mu) * inv * sc + d_mod[i];
    }
}

// split qkv, RMSNorm q/k, RoPE; q/k -> bf16 split [h][l][d], v fp32 [h][l][d]
__global__ void qkv_prep_kernel(const float* __restrict__ pe,
                                const float* __restrict__ qnw,
                                const float* __restrict__ knw) {
    int wg = blockIdx.x * 8 + (threadIdx.x >> 5);
    int lane = threadIdx.x & 31;
    int l = wg / NH, hd = wg % NH;
    const float* base = d_h + (size_t)l * W1N + hd * HD + lane * 4;
    float4 qv = *reinterpret_cast<const float4*>(base);
    float4 kv = *reinterpret_cast<const float4*>(base + HIDDEN);
    float4 vv = *reinterpret_cast<const float4*>(base + 2 * HIDDEN);

    float sq = qv.x * qv.x + qv.y * qv.y + qv.z * qv.z + qv.w * qv.w;
    float sk = kv.x * kv.x + kv.y * kv.y + kv.z * kv.z + kv.w * kv.w;
#pragma unroll
    for (int o = 16; o > 0; o >>= 1) {
        sq += __shfl_xor_sync(0xffffffffu, sq, o);
        sk += __shfl_xor_sync(0xffffffffu, sk, o);
    }
    float rq = rsqrtf(sq * (1.0f / HD) + 1e-6f);
    float rk = rsqrtf(sk * (1.0f / HD) + 1e-6f);
    float4 wq = *reinterpret_cast<const float4*>(qnw + lane * 4);
    float4 wk = *reinterpret_cast<const float4*>(knw + lane * 4);
    float q0 = qv.x * rq * wq.x, q1 = qv.y * rq * wq.y, q2 = qv.z * rq * wq.z, q3 = qv.w * rq * wq.w;
    float k0 = kv.x * rk * wk.x, k1 = kv.y * rk * wk.y, k2 = kv.z * rk * wk.z, k3 = kv.w * rk * wk.w;

    const float* pep = pe + (size_t)l * 256 + lane * 8;
    float4 p0 = *reinterpret_cast<const float4*>(pep);
    float4 p1 = *reinterpret_cast<const float4*>(pep + 4);
    float4 qo, ko;
    qo.x = p0.x * q0 + p0.y * q1;  qo.y = p0.z * q0 + p0.w * q1;
    qo.z = p1.x * q2 + p1.y * q3;  qo.w = p1.z * q2 + p1.w * q3;
    ko.x = p0.x * k0 + p0.y * k1;  ko.y = p0.z * k0 + p0.w * k1;
    ko.z = p1.x * k2 + p1.y * k3;  ko.w = p1.z * k2 + p1.w * k3;

    size_t o = ((size_t)hd * SEQ + l) * HD + lane * 4;
    __nv_bfloat162 hA, hB, lA, lB;
    uint2 uh, ul;
    hA.x = __float2bfloat16(qo.x); hA.y = __float2bfloat16(qo.y);
    hB.x = __float2bfloat16(qo.z); hB.y = __float2bfloat16(qo.w);
    lA.x = __float2bfloat16(qo.x - __bfloat162float(hA.x));
    lA.y = __float2bfloat16(qo.y - __bfloat162float(hA.y));
    lB.x = __float2bfloat16(qo.z - __bfloat162float(hB.x));
    lB.y = __float2bfloat16(qo.w - __bfloat162float(hB.y));
    uh.x = *(uint32_t*)&hA; uh.y = *(uint32_t*)&hB;
    ul.x = *(uint32_t*)&lA; ul.y = *(uint32_t*)&lB;
    *(uint2*)(d_qh + o) = uh; *(uint2*)(d_ql + o) = ul;

    hA.x = __float2bfloat16(ko.x); hA.y = __float2bfloat16(ko.y);
    hB.x = __float2bfloat16(ko.z); hB.y = __float2bfloat16(ko.w);
    lA.x = __float2bfloat16(ko.x - __bfloat162float(hA.x));
    lA.y = __float2bfloat16(ko.y - __bfloat162float(hA.y));
    lB.x = __float2bfloat16(ko.z - __bfloat162float(hB.x));
    lB.y = __float2bfloat16(ko.w - __bfloat162float(hB.y));
    uh.x = *(uint32_t*)&hA; uh.y = *(uint32_t*)&hB;
    ul.x = *(uint32_t*)&lA; ul.y = *(uint32_t*)&lB;
    *(uint2*)(d_kh + o) = uh; *(uint2*)(d_kl + o) = ul;

    *reinterpret_cast<float4*>(d_v + o) = vv;
}

// row softmax over d_s; outputs split bf16 probs to d_sh/d_sl
__global__ void softmax_split_kernel() {
    size_t rowoff = (size_t)blockIdx.x * SEQ;
    float* row = d_s + rowoff;
    int tid = threadIdx.x;
    float v[8];
    float m = -1e30f;
#pragma unroll
    for (int j = 0; j < 8; j++) { v[j] = row[tid + j * 256]; m = fmaxf(m, v[j]); }
    __shared__ float red[256];
    red[tid] = m;
    __syncthreads();
    for (int o = 128; o > 0; o >>= 1) {
        if (tid < o) red[tid] = fmaxf(red[tid], red[tid + o]);
        __syncthreads();
    }
    m = red[0];
    __syncthreads();
    float s = 0.0f;
#pragma unroll
    for (int j = 0; j < 8; j++) { v[j] = __expf(v[j] - m); s += v[j]; }
    red[tid] = s;
    __syncthreads();
    for (int o = 128; o > 0; o >>= 1) {
        if (tid < o) red[tid] += red[tid + o];
        __syncthreads();
    }
    float inv = 1.0f / red[0];
#pragma unroll
    for (int j = 0; j < 8; j++) {
        float p = v[j] * inv;
        __nv_bfloat16 h = __float2bfloat16(p);
        d_sh[rowoff + tid + j * 256] = h;
        d_sl[rowoff + tid + j * 256] = __float2bfloat16(p - __bfloat162float(h));
    }
}

// gelu(mlp half of h) -> split bf16 directly into a2 [:, HIDDEN:]
__global__ void gelu_split_kernel() {
    size_t g = ((size_t)blockIdx.x * 256 + threadIdx.x) * 2;  // over SEQ*MLPD, pairs
    size_t r = g / MLPD;
    int j = (int)(g % MLPD);
    float2 xv = *(const float2*)(d_h + r * W1N + 3 * HIDDEN + j);
    float t0 = tanhf(0.7978845608028654f * (xv.x + 0.044715f * xv.x * xv.x * xv.x));
    float t1 = tanhf(0.7978845608028654f * (xv.y + 0.044715f * xv.y * xv.y * xv.y));
    float g0 = 0.5f * xv.x * (1.0f + t0);
    float g1 = 0.5f * xv.y * (1.0f + t1);
    __nv_bfloat162 hp, lp;
    hp.x = __float2bfloat16(g0); hp.y = __float2bfloat16(g1);
    lp.x = __float2bfloat16(g0 - __bfloat162float(hp.x));
    lp.y = __float2bfloat16(g1 - __bfloat162float(hp.y));
    size_t o = r * CATN + HIDDEN + j;
    *(uint32_t*)(d_a2h + o) = *(uint32_t*)&hp;
    *(uint32_t*)(d_a2l + o) = *(uint32_t*)&lp;
}

// =================== driver =================================================
#define SMEM_NT8 (2 * (2 * ATILE + 2 * 256 * TSTR) * 2)  // 122880 B
#define SMEM_NT4 (2 * (2 * ATILE + 2 * 128 * TSTR) * 2)  // 81920 B
extern "C" void kernel_launch(void* const* d_in, const int* in_sizes, int n_in,
                              void* d_out, int out_size) {
    const float* x     = (const float*)d_in[0];
    const float* vec   = (const float*)d_in[1];
    const float* pe    = (const float*)d_in[2];
    const float* w1    = (const float*)d_in[3];
    const float* b1    = (const float*)d_in[4];
    const float* w2    = (const float*)d_in[5];
    const float* b2    = (const float*)d_in[6];
    const float* mod_w = (const float*)d_in[7];
    const float* mod_b = (const float*)d_in[8];
    const float* qnw   = (const float*)d_in[9];
    const float* knw   = (const float*)d_in[10];
    float* out = (float*)d_out;

    float *p_mod, *p_xmod, *p_h, *p_s;
    __nv_bfloat16 *p_a1h, *p_a1l, *p_a2h, *p_a2l, *p_w1th, *p_w1tl, *p_w2th, *p_w2tl;
    __nv_bfloat16 *p_qh, *p_ql, *p_kh, *p_kl, *p_vth, *p_vtl, *p_sh, *p_sl;
    cudaGetSymbolAddress((void**)&p_mod,  d_mod);
    cudaGetSymbolAddress((void**)&p_xmod, d_xmod);
    cudaGetSymbolAddress((void**)&p_h,    d_h);
    cudaGetSymbolAddress((void**)&p_s,    d_s);
    cudaGetSymbolAddress((void**)&p_a1h,  d_a1h);
    cudaGetSymbolAddress((void**)&p_a1l,  d_a1l);
    cudaGetSymbolAddress((void**)&p_a2h,  d_a2h);
    cudaGetSymbolAddress((void**)&p_a2l,  d_a2l);
    cudaGetSymbolAddress((void**)&p_w1th, d_w1th);
    cudaGetSymbolAddress((void**)&p_w1tl, d_w1tl);
    cudaGetSymbolAddress((void**)&p_w2th, d_w2th);
    cudaGetSymbolAddress((void**)&p_w2tl, d_w2tl);
    cudaGetSymbolAddress((void**)&p_qh,   d_qh);
    cudaGetSymbolAddress((void**)&p_ql,   d_ql);
    cudaGetSymbolAddress((void**)&p_kh,   d_kh);
    cudaGetSymbolAddress((void**)&p_kl,   d_kl);
    cudaGetSymbolAddress((void**)&p_vth,  d_vth);
    cudaGetSymbolAddress((void**)&p_vtl,  d_vtl);
    cudaGetSymbolAddress((void**)&p_sh,   d_sh);
    cudaGetSymbolAddress((void**)&p_sl,   d_sl);

    cudaFuncSetAttribute(hmma_gemm_kernel<8>, cudaFuncAttributeMaxDynamicSharedMemorySize, SMEM_NT8);
    cudaFuncSetAttribute(hmma_gemm_kernel<4>, cudaFuncAttributeMaxDynamicSharedMemorySize, SMEM_NT4);

    const float sc = 0.08838834764831845f;

    // 1) modulation + LN
    mod_gemv_kernel<<<MODN / 256, 256>>>(vec, mod_w, mod_b, p_mod);
    ln_mod_kernel<<<SEQ, 256>>>(x);
    // 2) operand prep for GEMM1 (+ weight transposes)
    split_kernel<<<(SEQ * HIDDEN) / 1024, 256>>>(p_xmod, p_a1h, p_a1l);
    transpose_split_kernel<<<dim3(W1N / 32, HIDDEN / 32), dim3(32, 8)>>>(w1, HIDDEN, W1N, p_w1th, p_w1tl);
    transpose_split_kernel<<<dim3(HIDDEN / 32, CATN / 32), dim3(32, 8)>>>(w2, CATN, HIDDEN, p_w2th, p_w2tl);
    // 3) GEMM1: h = x_mod @ w1 + b1   (128x256 tiles)
    hmma_gemm_kernel<8><<<dim3(SEQ / 128, W1N / 256, 1), 256, SMEM_NT8>>>(
        p_a1h, p_a1l, 0, p_w1th, p_w1tl, 0, p_h, W1N, 0,
        HIDDEN, 1.0f, 1, b1, nullptr, nullptr, nullptr, nullptr);
    // 4) qkv prep (q/k split bf16, v fp32)
    qkv_prep_kernel<<<SEQ * NH / 8, 256>>>(pe, qnw, knw);
    // 5) v transpose-split
    transpose_split_v_kernel<<<dim3(HD / 32, SEQ / 32, NH), dim3(32, 8)>>>();
    // 6) scores = (q @ k^T) * sc  (128x256 tiles, batched over heads)
    hmma_gemm_kernel<8><<<dim3(SEQ / 128, SEQ / 256, NH), 256, SMEM_NT8>>>(
        p_qh, p_ql, (long long)SEQ * HD, p_kh, p_kl, (long long)SEQ * HD,
        p_s, SEQ, (long long)SEQ * SEQ,
        HD, sc, 0, nullptr, nullptr, nullptr, nullptr, nullptr);
    // 7) softmax + split probs
    softmax_split_kernel<<<NH * SEQ, 256>>>();
    // 8) attn = probs @ v -> split directly into a2[:, h*HD:(h+1)*HD]  (128x128 tiles)
    hmma_gemm_kernel<4><<<dim3(SEQ / 128, 1, NH), 256, SMEM_NT4>>>(
        p_sh, p_sl, (long long)SEQ * SEQ, p_vth, p_vtl, (long long)HD * SEQ,
        nullptr, CATN, (long long)HD,
        SEQ, 1.0f, 3, nullptr, nullptr, nullptr, p_a2h, p_a2l);
    // 9) gelu -> split directly into a2[:, HIDDEN:]
    gelu_split_kernel<<<(SEQ * MLPD) / 512, 256>>>();
    // 10) GEMM2: out = x + gate * (cat @ w2 + b2)   (128x256 tiles)
    hmma_gemm_kernel<8><<<dim3(SEQ / 128, HIDDEN / 256, 1), 256, SMEM_NT8>>>(
        p_a2h, p_a2l, 0, p_w2th, p_w2tl, 0, out, HIDDEN, 0,
        CATN, 1.0f, 2, b2, x, p_mod + 2 * HIDDEN, nullptr, nullptr);
}

// round 14
// speedup vs baseline: 1.1460x; 1.1460x over previous
#include <cuda_runtime.h>
#include <cuda_bf16.h>
#include <math.h>
#include <stdint.h>

#define HIDDEN 3072
#define SEQ 2048
#define NH 24
#define HD 128
#define MLPD 12288
#define W1N 21504   // 3*HIDDEN + MLPD
#define CATN 15360  // HIDDEN + MLPD
#define MODN 9216   // 3*HIDDEN

// ---------------- scratch (device globals; no allocations allowed) ----------
__device__ float d_mod[MODN];
__device__ float d_xmod[(size_t)SEQ * HIDDEN];
__device__ float d_h[(size_t)SEQ * W1N];
__device__ float d_v[(size_t)NH * SEQ * HD];
__device__ float d_s[(size_t)NH * SEQ * SEQ];
// bf16 split operands (16B aligned for vector access)
__device__ __align__(16) __nv_bfloat16 d_a1h[(size_t)SEQ * HIDDEN];
__device__ __align__(16) __nv_bfloat16 d_a1l[(size_t)SEQ * HIDDEN];
__device__ __align__(16) __nv_bfloat16 d_a2h[(size_t)SEQ * CATN];
__device__ __align__(16) __nv_bfloat16 d_a2l[(size_t)SEQ * CATN];
__device__ __align__(16) __nv_bfloat16 d_w1th[(size_t)W1N * HIDDEN];  // [N=W1N, K=HIDDEN]
__device__ __align__(16) __nv_bfloat16 d_w1tl[(size_t)W1N * HIDDEN];
__device__ __align__(16) __nv_bfloat16 d_w2th[(size_t)HIDDEN * CATN]; // [N=HIDDEN, K=CATN]
__device__ __align__(16) __nv_bfloat16 d_w2tl[(size_t)HIDDEN * CATN];
// attention bf16 split operands
__device__ __align__(16) __nv_bfloat16 d_qh[(size_t)NH * SEQ * HD];
__device__ __align__(16) __nv_bfloat16 d_ql[(size_t)NH * SEQ * HD];
__device__ __align__(16) __nv_bfloat16 d_kh[(size_t)NH * SEQ * HD];
__device__ __align__(16) __nv_bfloat16 d_kl[(size_t)NH * SEQ * HD];
__device__ __align__(16) __nv_bfloat16 d_vth[(size_t)NH * HD * SEQ];
__device__ __align__(16) __nv_bfloat16 d_vtl[(size_t)NH * HD * SEQ];
__device__ __align__(16) __nv_bfloat16 d_sh[(size_t)NH * SEQ * SEQ];
__device__ __align__(16) __nv_bfloat16 d_sl[(size_t)NH * SEQ * SEQ];

// =================== helpers ================================================
__device__ __forceinline__ uint32_t smem_u32(const void* p) {
    uint32_t a;
    asm("{ .reg .u64 t; cvta.to.shared.u64 t, %1; cvt.u32.u64 %0, t; }" : "=r"(a) : "l"(p));
    return a;
}
__device__ __forceinline__ void cp_async16(void* sdst, const void* gsrc) {
    asm volatile("cp.async.cg.shared.global [%0], [%1], 16;"
                 :: "r"(smem_u32(sdst)), "l"(gsrc) : "memory");
}
__device__ __forceinline__ void mma16816(float* d, const uint32_t* a, const uint32_t* b) {
    asm volatile(
        "mma.sync.aligned.m16n8k16.row.col.f32.bf16.bf16.f32 "
        "{%0,%1,%2,%3}, {%4,%5,%6,%7}, {%8,%9}, {%0,%1,%2,%3};"
        : "+f"(d[0]), "+f"(d[1]), "+f"(d[2]), "+f"(d[3])
        : "r"(a[0]), "r"(a[1]), "r"(a[2]), "r"(a[3]), "r"(b[0]), "r"(b[1]));
}
__device__ __forceinline__ void ldsm_x4(uint32_t* r, uint32_t saddr) {
    asm volatile("ldmatrix.sync.aligned.m8n8.x4.shared.b16 {%0,%1,%2,%3}, [%4];"
                 : "=r"(r[0]), "=r"(r[1]), "=r"(r[2]), "=r"(r[3]) : "r"(saddr));
}

// =================== HMMA GEMM: C[M,N] = A[M,K] @ B^T (B:[N,K]) =============
// bf16 split-3: Ah*Bh + Al*Bh + Ah*Bl, fp32 accumulate.
// Double-buffered cp.async; ldmatrix fragment loads.
// CTA tile 128x128, warp layout 2x4, warp tile 64x32. 2 CTAs/SM.
// mode 0: C = alpha*acc ; 1: +bias ; 2: resid+gate*(acc+bias) ; 3: split->bf16
#define KC 32
#define TSTR 40                      // padded k-stride; 80B rows
#define ATILE (128 * TSTR)
#define STAGE (4 * ATILE)
#define HMMA_SMEM_BYTES (2 * STAGE * 2)   // 81920 B
__global__ void __launch_bounds__(256, 2) hmma_gemm_kernel(
    const __nv_bfloat16* __restrict__ Ah, const __nv_bfloat16* __restrict__ Al, long long sA,
    const __nv_bfloat16* __restrict__ Bh, const __nv_bfloat16* __restrict__ Bl, long long sB,
    float* __restrict__ C, int ldc, long long sC,
    int K, float alpha, int mode,
    const float* __restrict__ bias,
    const float* __restrict__ resid,
    const float* __restrict__ gate,
    __nv_bfloat16* __restrict__ outH,
    __nv_bfloat16* __restrict__ outL) {
    extern __shared__ __align__(16) __nv_bfloat16 smem[];

    const long long bz = blockIdx.z;
    Ah += bz * sA; Al += bz * sA;
    Bh += bz * sB; Bl += bz * sB;

    const int tid = threadIdx.x;
    const int wid = tid >> 5, lane = tid & 31;
    const int m0 = blockIdx.x * 128, n0 = blockIdx.y * 128;
    const int wm = (wid >> 2) * 64, wn = (wid & 3) * 32;

    float acc[4][4][4];
#pragma unroll
    for (int mt = 0; mt < 4; mt++)
#pragma unroll
        for (int nt = 0; nt < 4; nt++)
#pragma unroll
            for (int r = 0; r < 4; r++) acc[mt][nt][r] = 0.0f;

    const int lr = tid >> 2;          // 0..63 (loader)
    const int lc = (tid & 3) * 8;     // loader col offset
    const int nk = K / KC;

    // ldmatrix per-lane byte offsets (within a tile)
    const int lrow = lane & 7, lj1 = (lane >> 3) & 1, lj2 = lane >> 4;
    int aoff[4], boff[2];
#pragma unroll
    for (int mt = 0; mt < 4; mt++)
        aoff[mt] = ((wm + mt * 16 + lrow + lj1 * 8) * TSTR + lj2 * 8) * 2;
#pragma unroll
    for (int p = 0; p < 2; p++)
        boff[p] = ((wn + p * 16 + lj2 * 8 + lrow) * TSTR + lj1 * 8) * 2;

#define LOAD_STAGE(SB, KCOFF)                                                          \
    {                                                                                  \
        _Pragma("unroll")                                                              \
        for (int i = 0; i < 2; i++) {                                                  \
            int row = lr + i * 64;                                                     \
            int so = row * TSTR + lc;                                                  \
            cp_async16((SB) + so,             Ah + (size_t)(m0 + row) * K + (KCOFF) + lc); \
            cp_async16((SB) + ATILE + so,     Al + (size_t)(m0 + row) * K + (KCOFF) + lc); \
            cp_async16((SB) + 2 * ATILE + so, Bh + (size_t)(n0 + row) * K + (KCOFF) + lc); \
            cp_async16((SB) + 3 * ATILE + so, Bl + (size_t)(n0 + row) * K + (KCOFF) + lc); \
        }                                                                              \
        asm volatile("cp.async.commit_group;" ::: "memory");                           \
    }

    LOAD_STAGE(smem, 0)

    for (int it = 0; it < nk; it++) {
        asm volatile("cp.async.wait_group 0;" ::: "memory");
        __syncthreads();
        if (it + 1 < nk) {
            __nv_bfloat16* sb = smem + ((it + 1) & 1) * STAGE;
            LOAD_STAGE(sb, (it + 1) * KC)
        }
        const uint32_t uAh = smem_u32(smem + (it & 1) * STAGE);
        const uint32_t uAl = uAh + ATILE * 2;
        const uint32_t uBh = uAh + 2 * ATILE * 2;
        const uint32_t uBl = uAh + 3 * ATILE * 2;

#pragma unroll
        for (int ks = 0; ks < 2; ks++) {
            const int kb = ks * 32;   // bytes
            uint32_t ah[4][4], bh[2][4], xl[4][4], bl[2][4];
#pragma unroll
            for (int mt = 0; mt < 4; mt++) ldsm_x4(ah[mt], uAh + aoff[mt] + kb);
#pragma unroll
            for (int p = 0; p < 2; p++) ldsm_x4(bh[p], uBh + boff[p] + kb);
#pragma unroll
            for (int mt = 0; mt < 4; mt++)
#pragma unroll
                for (int nt = 0; nt < 4; nt++)
                    mma16816(acc[mt][nt], ah[mt], &bh[nt >> 1][(nt & 1) * 2]);
#pragma unroll
            for (int mt = 0; mt < 4; mt++) ldsm_x4(xl[mt], uAl + aoff[mt] + kb);
#pragma unroll
            for (int mt = 0; mt < 4; mt++)
#pragma unroll
                for (int nt = 0; nt < 4; nt++)
                    mma16816(acc[mt][nt], xl[mt], &bh[nt >> 1][(nt & 1) * 2]);
#pragma unroll
            for (int p = 0; p < 2; p++) ldsm_x4(bl[p], uBl + boff[p] + kb);
#pragma unroll
            for (int mt = 0; mt < 4; mt++)
#pragma unroll
                for (int nt = 0; nt < 4; nt++)
                    mma16816(acc[mt][nt], ah[mt], &bl[nt >> 1][(nt & 1) * 2]);
        }
    }
#undef LOAD_STAGE

    // epilogue
#pragma unroll
    for (int mt = 0; mt < 4; mt++) {
#pragma unroll
        for (int h = 0; h < 2; h++) {
            long long m = (long long)m0 + wm + mt * 16 + (lane >> 2) + h * 8;
            long long crow = bz * sC + m * ldc;
#pragma unroll
            for (int nt = 0; nt < 4; nt++) {
                int n = n0 + wn + nt * 8 + (lane & 3) * 2;
                float vx = acc[mt][nt][h * 2 + 0];
                float vy = acc[mt][nt][h * 2 + 1];
                if (mode == 0) {
                    vx *= alpha; vy *= alpha;
                    float2 o; o.x = vx; o.y = vy;
                    *(float2*)(C + crow + n) = o;
                } else if (mode == 3) {
                    __nv_bfloat162 hp, lp;
                    hp.x = __float2bfloat16(vx);
                    hp.y = __float2bfloat16(vy);
                    lp.x = __float2bfloat16(vx - __bfloat162float(hp.x));
                    lp.y = __float2bfloat16(vy - __bfloat162float(hp.y));
                    *(uint32_t*)(outH + crow + n) = *(uint32_t*)&hp;
                    *(uint32_t*)(outL + crow + n) = *(uint32_t*)&lp;
                } else {
                    vx += bias[n]; vy += bias[n + 1];
                    if (mode == 2) {
                        float2 xv = *(const float2*)(resid + m * ldc + n);
                        vx = fmaf(gate[n],     vx, xv.x);
                        vy = fmaf(gate[n + 1], vy, xv.y);
                    }
                    float2 o; o.x = vx; o.y = vy;
                    *(float2*)(C + crow + n) = o;
                }
            }
        }
    }
}

// =================== split / transpose prep kernels =========================
__global__ void split_kernel(const float* __restrict__ src,
                             __nv_bfloat16* __restrict__ dh,
                             __nv_bfloat16* __restrict__ dl) {
    size_t i = ((size_t)blockIdx.x * 256 + threadIdx.x) * 4;
    float4 v = *(const float4*)(src + i);
    __nv_bfloat162 hA, hB, lA, lB;
    hA.x = __float2bfloat16(v.x); hA.y = __float2bfloat16(v.y);
    hB.x = __float2bfloat16(v.z); hB.y = __float2bfloat16(v.w);
    lA.x = __float2bfloat16(v.x - __bfloat162float(hA.x));
    lA.y = __float2bfloat16(v.y - __bfloat162float(hA.y));
    lB.x = __float2bfloat16(v.z - __bfloat162float(hB.x));
    lB.y = __float2bfloat16(v.w - __bfloat162float(hB.y));
    uint2 uh, ul;
    uh.x = *(uint32_t*)&hA; uh.y = *(uint32_t*)&hB;
    ul.x = *(uint32_t*)&lA; ul.y = *(uint32_t*)&lB;
    *(uint2*)(dh + i) = uh;
    *(uint2*)(dl + i) = ul;
}

// src fp32 [R, Cc] -> dh/dl bf16 [Cc, R] (transposed, split)
__global__ void transpose_split_kernel(const float* __restrict__ src, int R, int Cc,
                                       __nv_bfloat16* __restrict__ dh,
                                       __nv_bfloat16* __restrict__ dl) {
    __shared__ float t[32][33];
    int c0 = blockIdx.x * 32, r0 = blockIdx.y * 32;
    int tx = threadIdx.x, ty = threadIdx.y;
#pragma unroll
    for (int i = 0; i < 4; i++)
        t[ty + 8 * i][tx] = src[(size_t)(r0 + ty + 8 * i) * Cc + c0 + tx];
    __syncthreads();
#pragma unroll
    for (int i = 0; i < 4; i++) {
        float v = t[tx][ty + 8 * i];
        __nv_bfloat16 h = __float2bfloat16(v);
        size_t o = (size_t)(c0 + ty + 8 * i) * R + r0 + tx;
        dh[o] = h;
        dl[o] = __float2bfloat16(v - __bfloat162float(h));
    }
}

// per-head: d_v [h][SEQ][HD] fp32 -> d_vt [h][HD][SEQ] bf16 split
__global__ void transpose_split_v_kernel() {
    __shared__ float t[32][33];
    int h = blockIdx.z;
    int c0 = blockIdx.x * 32;   // d
    int r0 = blockIdx.y * 32;   // seq
    int tx = threadIdx.x, ty = threadIdx.y;
    const float* src = d_v + (size_t)h * SEQ * HD;
#pragma unroll
    for (int i = 0; i < 4; i++)
        t[ty + 8 * i][tx] = src[(size_t)(r0 + ty + 8 * i) * HD + c0 + tx];
    __syncthreads();
    size_t base = (size_t)h * HD * SEQ;
#pragma unroll
    for (int i = 0; i < 4; i++) {
        float v = t[tx][ty + 8 * i];
        __nv_bfloat16 hh = __float2bfloat16(v);
        size_t o = base + (size_t)(c0 + ty + 8 * i) * SEQ + r0 + tx;
        d_vth[o] = hh;
        d_vtl[o] = __float2bfloat16(v - __bfloat162float(hh));
    }
}

// =================== small kernels =========================================
__global__ void mod_gemv_kernel(const float* __restrict__ vec,
                                const float* __restrict__ mod_w,
                                const float* __restrict__ mod_b,
                                float* __restrict__ mod) {
    __shared__ float sv[HIDDEN];
    for (int i = threadIdx.x; i < HIDDEN; i += 256) {
        float v = vec[i];
        sv[i] = v / (1.0f + expf(-v));
    }
    __syncthreads();
    int j = blockIdx.x * 256 + threadIdx.x;
    const float* wp = mod_w + j;
    float acc = 0.0f;
#pragma unroll 8
    for (int k = 0; k < HIDDEN; k++) acc = fmaf(sv[k], wp[(size_t)k * MODN], acc);
    mod[j] = acc + mod_b[j];
}

__global__ void ln_mod_kernel(const float* __restrict__ x) {
    int row = blockIdx.x;
    const float* xr = x + (size_t)row * HIDDEN;
    __shared__ float r1[256], r2[256];
    float s = 0.0f, s2 = 0.0f;
    for (int i = threadIdx.x; i < HIDDEN; i += 256) {
        float v = xr[i];
        s += v;
        s2 = fmaf(v, v, s2);
    }
    r1[threadIdx.x] = s; r2[threadIdx.x] = s2;
    __syncthreads();
    for (int o = 128; o > 0; o >>= 1) {
        if (threadIdx.x < o) { r1[threadIdx.x] += r1[threadIdx.x + o]; r2[threadIdx.x] += r2[threadIdx.x + o]; }
        __syncthreads();
    }
    float mu  = r1[0] * (1.0f / HIDDEN);
    float var = r2[0] * (1.0f / HIDDEN) - mu * mu;
    float inv = rsqrtf(var + 1e-6f);
    float* orow = d_xmod + (size_t)row * HIDDEN;
    for (int i = threadIdx.x; i < HIDDEN; i += 256) {
        float sc = 1.0f + d_mod[HIDDEN + i];
        orow[i] = (xr[i] - mu) * inv * sc + d_mod[i];
    }
}

// split qkv, RMSNorm q/k, RoPE; q/k -> bf16 split [h][l][d], v fp32 [h][l][d]
__global__ void qkv_prep_kernel(const float* __restrict__ pe,
                                const float* __restrict__ qnw,
                                const float* __restrict__ knw) {
    int wg = blockIdx.x * 8 + (threadIdx.x >> 5);
    int lane = threadIdx.x & 31;
    int l = wg / NH, hd = wg % NH;
    const float* base = d_h + (size_t)l * W1N + hd * HD + lane * 4;
    float4 qv = *reinterpret_cast<const float4*>(base);
    float4 kv = *reinterpret_cast<const float4*>(base + HIDDEN);
    float4 vv = *reinterpret_cast<const float4*>(base + 2 * HIDDEN);

    float sq = qv.x * qv.x + qv.y * qv.y + qv.z * qv.z + qv.w * qv.w;
    float sk = kv.x * kv.x + kv.y * kv.y + kv.z * kv.z + kv.w * kv.w;
#pragma unroll
    for (int o = 16; o > 0; o >>= 1) {
        sq += __shfl_xor_sync(0xffffffffu, sq, o);
        sk += __shfl_xor_sync(0xffffffffu, sk, o);
    }
    float rq = rsqrtf(sq * (1.0f / HD) + 1e-6f);
    float rk = rsqrtf(sk * (1.0f / HD) + 1e-6f);
    float4 wq = *reinterpret_cast<const float4*>(qnw + lane * 4);
    float4 wk = *reinterpret_cast<const float4*>(knw + lane * 4);
    float q0 = qv.x * rq * wq.x, q1 = qv.y * rq * wq.y, q2 = qv.z * rq * wq.z, q3 = qv.w * rq * wq.w;
    float k0 = kv.x * rk * wk.x, k1 = kv.y * rk * wk.y, k2 = kv.z * rk * wk.z, k3 = kv.w * rk * wk.w;

    const float* pep = pe + (size_t)l * 256 + lane * 8;
    float4 p0 = *reinterpret_cast<const float4*>(pep);
    float4 p1 = *reinterpret_cast<const float4*>(pep + 4);
    float4 qo, ko;
    qo.x = p0.x * q0 + p0.y * q1;  qo.y = p0.z * q0 + p0.w * q1;
    qo.z = p1.x * q2 + p1.y * q3;  qo.w = p1.z * q2 + p1.w * q3;
    ko.x = p0.x * k0 + p0.y * k1;  ko.y = p0.z * k0 + p0.w * k1;
    ko.z = p1.x * k2 + p1.y * k3;  ko.w = p1.z * k2 + p1.w * k3;

    size_t o = ((size_t)hd * SEQ + l) * HD + lane * 4;
    __nv_bfloat162 hA, hB, lA, lB;
    uint2 uh, ul;
    hA.x = __float2bfloat16(qo.x); hA.y = __float2bfloat16(qo.y);
    hB.x = __float2bfloat16(qo.z); hB.y = __float2bfloat16(qo.w);
    lA.x = __float2bfloat16(qo.x - __bfloat162float(hA.x));
    lA.y = __float2bfloat16(qo.y - __bfloat162float(hA.y));
    lB.x = __float2bfloat16(qo.z - __bfloat162float(hB.x));
    lB.y = __float2bfloat16(qo.w - __bfloat162float(hB.y));
    uh.x = *(uint32_t*)&hA; uh.y = *(uint32_t*)&hB;
    ul.x = *(uint32_t*)&lA; ul.y = *(uint32_t*)&lB;
    *(uint2*)(d_qh + o) = uh; *(uint2*)(d_ql + o) = ul;

    hA.x = __float2bfloat16(ko.x); hA.y = __float2bfloat16(ko.y);
    hB.x = __float2bfloat16(ko.z); hB.y = __float2bfloat16(ko.w);
    lA.x = __float2bfloat16(ko.x - __bfloat162float(hA.x));
    lA.y = __float2bfloat16(ko.y - __bfloat162float(hA.y));
    lB.x = __float2bfloat16(ko.z - __bfloat162float(hB.x));
    lB.y = __float2bfloat16(ko.w - __bfloat162float(hB.y));
    uh.x = *(uint32_t*)&hA; uh.y = *(uint32_t*)&hB;
    ul.x = *(uint32_t*)&lA; ul.y = *(uint32_t*)&lB;
    *(uint2*)(d_kh + o) = uh; *(uint2*)(d_kl + o) = ul;

    *reinterpret_cast<float4*>(d_v + o) = vv;
}

// row softmax over d_s; outputs split bf16 probs to d_sh/d_sl
__global__ void softmax_split_kernel() {
    size_t rowoff = (size_t)blockIdx.x * SEQ;
    float* row = d_s + rowoff;
    int tid = threadIdx.x;
    float v[8];
    float m = -1e30f;
#pragma unroll
    for (int j = 0; j < 8; j++) { v[j] = row[tid + j * 256]; m = fmaxf(m, v[j]); }
    __shared__ float red[256];
    red[tid] = m;
    __syncthreads();
    for (int o = 128; o > 0; o >>= 1) {
        if (tid < o) red[tid] = fmaxf(red[tid], red[tid + o]);
        __syncthreads();
    }
    m = red[0];
    __syncthreads();
    float s = 0.0f;
#pragma unroll
    for (int j = 0; j < 8; j++) { v[j] = __expf(v[j] - m); s += v[j]; }
    red[tid] = s;
    __syncthreads();
    for (int o = 128; o > 0; o >>= 1) {
        if (tid < o) red[tid] += red[tid + o];
        __syncthreads();
    }
    float inv = 1.0f / red[0];
#pragma unroll
    for (int j = 0; j < 8; j++) {
        float p = v[j] * inv;
        __nv_bfloat16 h = __float2bfloat16(p);
        d_sh[rowoff + tid + j * 256] = h;
        d_sl[rowoff + tid + j * 256] = __float2bfloat16(p - __bfloat162float(h));
    }
}

// gelu(mlp half of h) -> split bf16 directly into a2 [:, HIDDEN:]
__global__ void gelu_split_kernel() {
    size_t g = ((size_t)blockIdx.x * 256 + threadIdx.x) * 2;
    size_t r = g / MLPD;
    int j = (int)(g % MLPD);
    float2 xv = *(const float2*)(d_h + r * W1N + 3 * HIDDEN + j);
    float t0 = tanhf(0.7978845608028654f * (xv.x + 0.044715f * xv.x * xv.x * xv.x));
    float t1 = tanhf(0.7978845608028654f * (xv.y + 0.044715f * xv.y * xv.y * xv.y));
    float g0 = 0.5f * xv.x * (1.0f + t0);
    float g1 = 0.5f * xv.y * (1.0f + t1);
    __nv_bfloat162 hp, lp;
    hp.x = __float2bfloat16(g0); hp.y = __float2bfloat16(g1);
    lp.x = __float2bfloat16(g0 - __bfloat162float(hp.x));
    lp.y = __float2bfloat16(g1 - __bfloat162float(hp.y));
    size_t o = r * CATN + HIDDEN + j;
    *(uint32_t*)(d_a2h + o) = *(uint32_t*)&hp;
    *(uint32_t*)(d_a2l + o) = *(uint32_t*)&lp;
}

// =================== driver =================================================
extern "C" void kernel_launch(void* const* d_in, const int* in_sizes, int n_in,
                              void* d_out, int out_size) {
    const float* x     = (const float*)d_in[0];
    const float* vec   = (const float*)d_in[1];
    const float* pe    = (const float*)d_in[2];
    const float* w1    = (const float*)d_in[3];
    const float* b1    = (const float*)d_in[4];
    const float* w2    = (const float*)d_in[5];
    const float* b2    = (const float*)d_in[6];
    const float* mod_w = (const float*)d_in[7];
    const float* mod_b = (const float*)d_in[8];
    const float* qnw   = (const float*)d_in[9];
    const float* knw   = (const float*)d_in[10];
    float* out = (float*)d_out;

    float *p_mod, *p_xmod, *p_h, *p_s;
    __nv_bfloat16 *p_a1h, *p_a1l, *p_a2h, *p_a2l, *p_w1th, *p_w1tl, *p_w2th, *p_w2tl;
    __nv_bfloat16 *p_qh, *p_ql, *p_kh, *p_kl, *p_vth, *p_vtl, *p_sh, *p_sl;
    cudaGetSymbolAddress((void**)&p_mod,  d_mod);
    cudaGetSymbolAddress((void**)&p_xmod, d_xmod);
    cudaGetSymbolAddress((void**)&p_h,    d_h);
    cudaGetSymbolAddress((void**)&p_s,    d_s);
    cudaGetSymbolAddress((void**)&p_a1h,  d_a1h);
    cudaGetSymbolAddress((void**)&p_a1l,  d_a1l);
    cudaGetSymbolAddress((void**)&p_a2h,  d_a2h);
    cudaGetSymbolAddress((void**)&p_a2l,  d_a2l);
    cudaGetSymbolAddress((void**)&p_w1th, d_w1th);
    cudaGetSymbolAddress((void**)&p_w1tl, d_w1tl);
    cudaGetSymbolAddress((void**)&p_w2th, d_w2th);
    cudaGetSymbolAddress((void**)&p_w2tl, d_w2tl);
    cudaGetSymbolAddress((void**)&p_qh,   d_qh);
    cudaGetSymbolAddress((void**)&p_ql,   d_ql);
    cudaGetSymbolAddress((void**)&p_kh,   d_kh);
    cudaGetSymbolAddress((void**)&p_kl,   d_kl);
    cudaGetSymbolAddress((void**)&p_vth,  d_vth);
    cudaGetSymbolAddress((void**)&p_vtl,  d_vtl);
    cudaGetSymbolAddress((void**)&p_sh,   d_sh);
    cudaGetSymbolAddress((void**)&p_sl,   d_sl);

    cudaFuncSetAttribute(hmma_gemm_kernel, cudaFuncAttributeMaxDynamicSharedMemorySize,
                         HMMA_SMEM_BYTES);

    const float sc = 0.08838834764831845f;

    // 1) modulation + LN
    mod_gemv_kernel<<<MODN / 256, 256>>>(vec, mod_w, mod_b, p_mod);
    ln_mod_kernel<<<SEQ, 256>>>(x);
    // 2) operand prep for GEMM1 (+ weight transposes)
    split_kernel<<<(SEQ * HIDDEN) / 1024, 256>>>(p_xmod, p_a1h, p_a1l);
    transpose_split_kernel<<<dim3(W1N / 32, HIDDEN / 32), dim3(32, 8)>>>(w1, HIDDEN, W1N, p_w1th, p_w1tl);
    transpose_split_kernel<<<dim3(HIDDEN / 32, CATN / 32), dim3(32, 8)>>>(w2, CATN, HIDDEN, p_w2th, p_w2tl);
    // 3) GEMM1: h = x_mod @ w1 + b1
    hmma_gemm_kernel<<<dim3(SEQ / 128, W1N / 128, 1), 256, HMMA_SMEM_BYTES>>>(
        p_a1h, p_a1l, 0, p_w1th, p_w1tl, 0, p_h, W1N, 0,
        HIDDEN, 1.0f, 1, b1, nullptr, nullptr, nullptr, nullptr);
    // 4) qkv prep (q/k split bf16, v fp32)
    qkv_prep_kernel<<<SEQ * NH / 8, 256>>>(pe, qnw, knw);
    // 5) v transpose-split
    transpose_split_v_kernel<<<dim3(HD / 32, SEQ / 32, NH), dim3(32, 8)>>>();
    // 6) scores = (q @ k^T) * sc  (batched over heads)
    hmma_gemm_kernel<<<dim3(SEQ / 128, SEQ / 128, NH), 256, HMMA_SMEM_BYTES>>>(
        p_qh, p_ql, (long long)SEQ * HD, p_kh, p_kl, (long long)SEQ * HD,
        p_s, SEQ, (long long)SEQ * SEQ,
        HD, sc, 0, nullptr, nullptr, nullptr, nullptr, nullptr);
    // 7) softmax + split probs
    softmax_split_kernel<<<NH * SEQ, 256>>>();
    // 8) attn = probs @ v -> split directly into a2[:, h*HD:(h+1)*HD]
    hmma_gemm_kernel<<<dim3(SEQ / 128, 1, NH), 256, HMMA_SMEM_BYTES>>>(
        p_sh, p_sl, (long long)SEQ * SEQ, p_vth, p_vtl, (long long)HD * SEQ,
        nullptr, CATN, (long long)HD,
        SEQ, 1.0f, 3, nullptr, nullptr, nullptr, p_a2h, p_a2l);
    // 9) gelu -> split directly into a2[:, HIDDEN:]
    gelu_split_kernel<<<(SEQ * MLPD) / 512, 256>>>();
    // 10) GEMM2: out = x + gate * (cat @ w2 + b2)
    hmma_gemm_kernel<<<dim3(SEQ / 128, HIDDEN / 128, 1), 256, HMMA_SMEM_BYTES>>>(
        p_a2h, p_a2l, 0, p_w2th, p_w2tl, 0, out, HIDDEN, 0,
        CATN, 1.0f, 2, b2, x, p_mod + 2 * HIDDEN, nullptr, nullptr);
}

// round 16
// speedup vs baseline: 1.2451x; 1.0865x over previous
#include <cuda_runtime.h>
#include <cuda_bf16.h>
#include <math.h>
#include <stdint.h>

#define HIDDEN 3072
#define SEQ 2048
#define NH 24
#define HD 128
#define MLPD 12288
#define W1N 21504   // 3*HIDDEN + MLPD
#define CATN 15360  // HIDDEN + MLPD
#define MODN 9216   // 3*HIDDEN

// ---------------- scratch (device globals; no allocations allowed) ----------
__device__ float d_mod[MODN];
__device__ float d_xmod[(size_t)SEQ * HIDDEN];   // reused as GEMM2a partial later
__device__ float d_h[(size_t)SEQ * W1N];
__device__ float d_v[(size_t)NH * SEQ * HD];
__device__ float d_s[(size_t)NH * SEQ * SEQ];
// bf16 split operands (16B aligned for vector access)
__device__ __align__(16) __nv_bfloat16 d_a1h[(size_t)SEQ * HIDDEN];
__device__ __align__(16) __nv_bfloat16 d_a1l[(size_t)SEQ * HIDDEN];
__device__ __align__(16) __nv_bfloat16 d_a2h[(size_t)SEQ * CATN];
__device__ __align__(16) __nv_bfloat16 d_a2l[(size_t)SEQ * CATN];
__device__ __align__(16) __nv_bfloat16 d_w1th[(size_t)W1N * HIDDEN];  // [N=W1N, K=HIDDEN]
__device__ __align__(16) __nv_bfloat16 d_w1tl[(size_t)W1N * HIDDEN];
__device__ __align__(16) __nv_bfloat16 d_w2th[(size_t)HIDDEN * CATN]; // [N=HIDDEN, K=CATN]
__device__ __align__(16) __nv_bfloat16 d_w2tl[(size_t)HIDDEN * CATN];
// attention bf16 split operands
__device__ __align__(16) __nv_bfloat16 d_qh[(size_t)NH * SEQ * HD];
__device__ __align__(16) __nv_bfloat16 d_ql[(size_t)NH * SEQ * HD];
__device__ __align__(16) __nv_bfloat16 d_kh[(size_t)NH * SEQ * HD];
__device__ __align__(16) __nv_bfloat16 d_kl[(size_t)NH * SEQ * HD];
__device__ __align__(16) __nv_bfloat16 d_vth[(size_t)NH * HD * SEQ];
__device__ __align__(16) __nv_bfloat16 d_vtl[(size_t)NH * HD * SEQ];
__device__ __align__(16) __nv_bfloat16 d_sh[(size_t)NH * SEQ * SEQ];
__device__ __align__(16) __nv_bfloat16 d_sl[(size_t)NH * SEQ * SEQ];

// =================== helpers ================================================
__device__ __forceinline__ uint32_t smem_u32(const void* p) {
    uint32_t a;
    asm("{ .reg .u64 t; cvta.to.shared.u64 t, %1; cvt.u32.u64 %0, t; }" : "=r"(a) : "l"(p));
    return a;
}
__device__ __forceinline__ void cp_async16(void* sdst, const void* gsrc) {
    asm volatile("cp.async.cg.shared.global [%0], [%1], 16;"
                 :: "r"(smem_u32(sdst)), "l"(gsrc) : "memory");
}
__device__ __forceinline__ void mma16816(float* d, const uint32_t* a, const uint32_t* b) {
    asm volatile(
        "mma.sync.aligned.m16n8k16.row.col.f32.bf16.bf16.f32 "
        "{%0,%1,%2,%3}, {%4,%5,%6,%7}, {%8,%9}, {%0,%1,%2,%3};"
        : "+f"(d[0]), "+f"(d[1]), "+f"(d[2]), "+f"(d[3])
        : "r"(a[0]), "r"(a[1]), "r"(a[2]), "r"(a[3]), "r"(b[0]), "r"(b[1]));
}
__device__ __forceinline__ void ldsm_x4(uint32_t* r, uint32_t saddr) {
    asm volatile("ldmatrix.sync.aligned.m8n8.x4.shared.b16 {%0,%1,%2,%3}, [%4];"
                 : "=r"(r[0]), "=r"(r[1]), "=r"(r[2]), "=r"(r[3]) : "r"(saddr));
}

// =================== HMMA GEMM: C[M,N] = A[M,K] @ B^T (B:[N,K]) =============
// bf16 split-3: Ah*Bh + Al*Bh + Ah*Bl, fp32 accumulate.
// Double-buffered cp.async; ldmatrix fragment loads.
// CTA tile 128x128, warp layout 2x4, warp tile 64x32. 2 CTAs/SM.
// lda/ldb decoupled from K (row strides of A and B).
// mode 0: C = alpha*acc
// mode 1: C = acc + bias
// mode 2: C = resid + gate*(acc + bias)
// mode 3: split(acc) -> outH/outL bf16
// mode 4: C = resid + gate*(acc + tmpC + bias)
#define KC 32
#define TSTR 40                      // padded k-stride; 80B rows
#define ATILE (128 * TSTR)
#define STAGE (4 * ATILE)
#define HMMA_SMEM_BYTES (2 * STAGE * 2)   // 81920 B
__global__ void __launch_bounds__(256, 2) hmma_gemm_kernel(
    const __nv_bfloat16* __restrict__ Ah, const __nv_bfloat16* __restrict__ Al,
    int lda, long long sA,
    const __nv_bfloat16* __restrict__ Bh, const __nv_bfloat16* __restrict__ Bl,
    int ldb, long long sB,
    float* __restrict__ C, int ldc, long long sC,
    int K, float alpha, int mode,
    const float* __restrict__ bias,
    const float* __restrict__ resid,
    const float* __restrict__ gate,
    __nv_bfloat16* __restrict__ outH,
    __nv_bfloat16* __restrict__ outL,
    const float* __restrict__ tmpC) {
    extern __shared__ __align__(16) __nv_bfloat16 smem[];

    const long long bz = blockIdx.z;
    Ah += bz * sA; Al += bz * sA;
    Bh += bz * sB; Bl += bz * sB;

    const int tid = threadIdx.x;
    const int wid = tid >> 5, lane = tid & 31;
    const int m0 = blockIdx.x * 128, n0 = blockIdx.y * 128;
    const int wm = (wid >> 2) * 64, wn = (wid & 3) * 32;

    float acc[4][4][4];
#pragma unroll
    for (int mt = 0; mt < 4; mt++)
#pragma unroll
        for (int nt = 0; nt < 4; nt++)
#pragma unroll
            for (int r = 0; r < 4; r++) acc[mt][nt][r] = 0.0f;

    const int lr = tid >> 2;          // 0..63 (loader)
    const int lc = (tid & 3) * 8;     // loader col offset
    const int nk = K / KC;

    // ldmatrix per-lane byte offsets (within a tile)
    const int lrow = lane & 7, lj1 = (lane >> 3) & 1, lj2 = lane >> 4;
    int aoff[4], boff[2];
#pragma unroll
    for (int mt = 0; mt < 4; mt++)
        aoff[mt] = ((wm + mt * 16 + lrow + lj1 * 8) * TSTR + lj2 * 8) * 2;
#pragma unroll
    for (int p = 0; p < 2; p++)
        boff[p] = ((wn + p * 16 + lj2 * 8 + lrow) * TSTR + lj1 * 8) * 2;

#define LOAD_STAGE(SB, KCOFF)                                                          \
    {                                                                                  \
        _Pragma("unroll")                                                              \
        for (int i = 0; i < 2; i++) {                                                  \
            int row = lr + i * 64;                                                     \
            int so = row * TSTR + lc;                                                  \
            cp_async16((SB) + so,             Ah + (size_t)(m0 + row) * lda + (KCOFF) + lc); \
            cp_async16((SB) + ATILE + so,     Al + (size_t)(m0 + row) * lda + (KCOFF) + lc); \
            cp_async16((SB) + 2 * ATILE + so, Bh + (size_t)(n0 + row) * ldb + (KCOFF) + lc); \
            cp_async16((SB) + 3 * ATILE + so, Bl + (size_t)(n0 + row) * ldb + (KCOFF) + lc); \
        }                                                                              \
        asm volatile("cp.async.commit_group;" ::: "memory");                           \
    }

    LOAD_STAGE(smem, 0)

    for (int it = 0; it < nk; it++) {
        asm volatile("cp.async.wait_group 0;" ::: "memory");
        __syncthreads();
        if (it + 1 < nk) {
            __nv_bfloat16* sb = smem + ((it + 1) & 1) * STAGE;
            LOAD_STAGE(sb, (it + 1) * KC)
        }
        const uint32_t uAh = smem_u32(smem + (it & 1) * STAGE);
        const uint32_t uAl = uAh + ATILE * 2;
        const uint32_t uBh = uAh + 2 * ATILE * 2;
        const uint32_t uBl = uAh + 3 * ATILE * 2;

#pragma unroll
        for (int ks = 0; ks < 2; ks++) {
            const int kb = ks * 32;   // bytes
            uint32_t ah[4][4], bh[2][4], xl[4][4], bl[2][4];
#pragma unroll
            for (int mt = 0; mt < 4; mt++) ldsm_x4(ah[mt], uAh + aoff[mt] + kb);
#pragma unroll
            for (int p = 0; p < 2; p++) ldsm_x4(bh[p], uBh + boff[p] + kb);
#pragma unroll
            for (int mt = 0; mt < 4; mt++)
#pragma unroll
                for (int nt = 0; nt < 4; nt++)
                    mma16816(acc[mt][nt], ah[mt], &bh[nt >> 1][(nt & 1) * 2]);
#pragma unroll
            for (int mt = 0; mt < 4; mt++) ldsm_x4(xl[mt], uAl + aoff[mt] + kb);
#pragma unroll
            for (int mt = 0; mt < 4; mt++)
#pragma unroll
                for (int nt = 0; nt < 4; nt++)
                    mma16816(acc[mt][nt], xl[mt], &bh[nt >> 1][(nt & 1) * 2]);
#pragma unroll
            for (int p = 0; p < 2; p++) ldsm_x4(bl[p], uBl + boff[p] + kb);
#pragma unroll
            for (int mt = 0; mt < 4; mt++)
#pragma unroll
                for (int nt = 0; nt < 4; nt++)
                    mma16816(acc[mt][nt], ah[mt], &bl[nt >> 1][(nt & 1) * 2]);
        }
    }
#undef LOAD_STAGE

    // epilogue
#pragma unroll
    for (int mt = 0; mt < 4; mt++) {
#pragma unroll
        for (int h = 0; h < 2; h++) {
            long long m = (long long)m0 + wm + mt * 16 + (lane >> 2) + h * 8;
            long long crow = bz * sC + m * ldc;
#pragma unroll
            for (int nt = 0; nt < 4; nt++) {
                int n = n0 + wn + nt * 8 + (lane & 3) * 2;
                float vx = acc[mt][nt][h * 2 + 0];
                float vy = acc[mt][nt][h * 2 + 1];
                if (mode == 0) {
                    vx *= alpha; vy *= alpha;
                    float2 o; o.x = vx; o.y = vy;
                    *(float2*)(C + crow + n) = o;
                } else if (mode == 3) {
                    __nv_bfloat162 hp, lp;
                    hp.x = __float2bfloat16(vx);
                    hp.y = __float2bfloat16(vy);
                    lp.x = __float2bfloat16(vx - __bfloat162float(hp.x));
                    lp.y = __float2bfloat16(vy - __bfloat162float(hp.y));
                    *(uint32_t*)(outH + crow + n) = *(uint32_t*)&hp;
                    *(uint32_t*)(outL + crow + n) = *(uint32_t*)&lp;
                } else {
                    if (mode == 4) {
                        float2 tv = *(const float2*)(tmpC + m * ldc + n);
                        vx += tv.x; vy += tv.y;
                    }
                    vx += bias[n]; vy += bias[n + 1];
                    if (mode >= 2) {
                        float2 xv = *(const float2*)(resid + m * ldc + n);
                        vx = fmaf(gate[n],     vx, xv.x);
                        vy = fmaf(gate[n + 1], vy, xv.y);
                    }
                    float2 o; o.x = vx; o.y = vy;
                    *(float2*)(C + crow + n) = o;
                }
            }
        }
    }
}

// =================== split / transpose prep kernels =========================
__global__ void split_kernel(const float* __restrict__ src,
                             __nv_bfloat16* __restrict__ dh,
                             __nv_bfloat16* __restrict__ dl) {
    size_t i = ((size_t)blockIdx.x * 256 + threadIdx.x) * 4;
    float4 v = *(const float4*)(src + i);
    __nv_bfloat162 hA, hB, lA, lB;
    hA.x = __float2bfloat16(v.x); hA.y = __float2bfloat16(v.y);
    hB.x = __float2bfloat16(v.z); hB.y = __float2bfloat16(v.w);
    lA.x = __float2bfloat16(v.x - __bfloat162float(hA.x));
    lA.y = __float2bfloat16(v.y - __bfloat162float(hA.y));
    lB.x = __float2bfloat16(v.z - __bfloat162float(hB.x));
    lB.y = __float2bfloat16(v.w - __bfloat162float(hB.y));
    uint2 uh, ul;
    uh.x = *(uint32_t*)&hA; uh.y = *(uint32_t*)&hB;
    ul.x = *(uint32_t*)&lA; ul.y = *(uint32_t*)&lB;
    *(uint2*)(dh + i) = uh;
    *(uint2*)(dl + i) = ul;
}

// src fp32 [R, Cc] -> dh/dl bf16 [Cc, R] (transposed, split)
__global__ void transpose_split_kernel(const float* __restrict__ src, int R, int Cc,
                                       __nv_bfloat16* __restrict__ dh,
                                       __nv_bfloat16* __restrict__ dl) {
    __shared__ float t[32][33];
    int c0 = blockIdx.x * 32, r0 = blockIdx.y * 32;
    int tx = threadIdx.x, ty = threadIdx.y;
#pragma unroll
    for (int i = 0; i < 4; i++)
        t[ty + 8 * i][tx] = src[(size_t)(r0 + ty + 8 * i) * Cc + c0 + tx];
    __syncthreads();
#pragma unroll
    for (int i = 0; i < 4; i++) {
        float v = t[tx][ty + 8 * i];
        __nv_bfloat16 h = __float2bfloat16(v);
        size_t o = (size_t)(c0 + ty + 8 * i) * R + r0 + tx;
        dh[o] = h;
        dl[o] = __float2bfloat16(v - __bfloat162float(h));
    }
}

// per-head: d_v [h][SEQ][HD] fp32 -> d_vt [h][HD][SEQ] bf16 split
__global__ void transpose_split_v_kernel() {
    __shared__ float t[32][33];
    int h = blockIdx.z;
    int c0 = blockIdx.x * 32;   // d
    int r0 = blockIdx.y * 32;   // seq
    int tx = threadIdx.x, ty = threadIdx.y;
    const float* src = d_v + (size_t)h * SEQ * HD;
#pragma unroll
    for (int i = 0; i < 4; i++)
        t[ty + 8 * i][tx] = src[(size_t)(r0 + ty + 8 * i) * HD + c0 + tx];
    __syncthreads();
    size_t base = (size_t)h * HD * SEQ;
#pragma unroll
    for (int i = 0; i < 4; i++) {
        float v = t[tx][ty + 8 * i];
        __nv_bfloat16 hh = __float2bfloat16(v);
        size_t o = base + (size_t)(c0 + ty + 8 * i) * SEQ + r0 + tx;
        d_vth[o] = hh;
        d_vtl[o] = __float2bfloat16(v - __bfloat162float(hh));
    }
}

// =================== small kernels =========================================
__global__ void mod_gemv_kernel(const float* __restrict__ vec,
                                const float* __restrict__ mod_w,
                                const float* __restrict__ mod_b,
                                float* __restrict__ mod) {
    __shared__ float sv[HIDDEN];
    for (int i = threadIdx.x; i < HIDDEN; i += 256) {
        float v = vec[i];
        sv[i] = v / (1.0f + expf(-v));
    }
    __syncthreads();
    int j = blockIdx.x * 256 + threadIdx.x;
    const float* wp = mod_w + j;
    float acc = 0.0f;
#pragma unroll 8
    for (int k = 0; k < HIDDEN; k++) acc = fmaf(sv[k], wp[(size_t)k * MODN], acc);
    mod[j] = acc + mod_b[j];
}

__global__ void ln_mod_kernel(const float* __restrict__ x) {
    int row = blockIdx.x;
    const float* xr = x + (size_t)row * HIDDEN;
    __shared__ float r1[256], r2[256];
    float s = 0.0f, s2 = 0.0f;
    for (int i = threadIdx.x; i < HIDDEN; i += 256) {
        float v = xr[i];
        s += v;
        s2 = fmaf(v, v, s2);
    }
    r1[threadIdx.x] = s; r2[threadIdx.x] = s2;
    __syncthreads();
    for (int o = 128; o > 0; o >>= 1) {
        if (threadIdx.x < o) { r1[threadIdx.x] += r1[threadIdx.x + o]; r2[threadIdx.x] += r2[threadIdx.x + o]; }
        __syncthreads();
    }
    float mu  = r1[0] * (1.0f / HIDDEN);
    float var = r2[0] * (1.0f / HIDDEN) - mu * mu;
    float inv = rsqrtf(var + 1e-6f);
    float* orow = d_xmod + (size_t)row * HIDDEN;
    for (int i = threadIdx.x; i < HIDDEN; i += 256) {
        float sc = 1.0f + d_mod[HIDDEN + i];
        orow[i] = (xr[i] - mu) * inv * sc + d_mod[i];
    }
}

// split qkv, RMSNorm q/k, RoPE; q/k -> bf16 split [h][l][d], v fp32 [h][l][d]
__global__ void qkv_prep_kernel(const float* __restrict__ pe,
                                const float* __restrict__ qnw,
                                const float* __restrict__ knw) {
    int wg = blockIdx.x * 8 + (threadIdx.x >> 5);
    int lane = threadIdx.x & 31;
    int l = wg / NH, hd = wg % NH;
    const float* base = d_h + (size_t)l * W1N + hd * HD + lane * 4;
    float4 qv = *reinterpret_cast<const float4*>(base);
    float4 kv = *reinterpret_cast<const float4*>(base + HIDDEN);
    float4 vv = *reinterpret_cast<const float4*>(base + 2 * HIDDEN);

    float sq = qv.x * qv.x + qv.y * qv.y + qv.z * qv.z + qv.w * qv.w;
    float sk = kv.x * kv.x + kv.y * kv.y + kv.z * kv.z + kv.w * kv.w;
#pragma unroll
    for (int o = 16; o > 0; o >>= 1) {
        sq += __shfl_xor_sync(0xffffffffu, sq, o);
        sk += __shfl_xor_sync(0xffffffffu, sk, o);
    }
    float rq = rsqrtf(sq * (1.0f / HD) + 1e-6f);
    float rk = rsqrtf(sk * (1.0f / HD) + 1e-6f);
    float4 wq = *reinterpret_cast<const float4*>(qnw + lane * 4);
    float4 wk = *reinterpret_cast<const float4*>(knw + lane * 4);
    float q0 = qv.x * rq * wq.x, q1 = qv.y * rq * wq.y, q2 = qv.z * rq * wq.z, q3 = qv.w * rq * wq.w;
    float k0 = kv.x * rk * wk.x, k1 = kv.y * rk * wk.y, k2 = kv.z * rk * wk.z, k3 = kv.w * rk * wk.w;

    const float* pep = pe + (size_t)l * 256 + lane * 8;
    float4 p0 = *reinterpret_cast<const float4*>(pep);
    float4 p1 = *reinterpret_cast<const float4*>(pep + 4);
    float4 qo, ko;
    qo.x = p0.x * q0 + p0.y * q1;  qo.y = p0.z * q0 + p0.w * q1;
    qo.z = p1.x * q2 + p1.y * q3;  qo.w = p1.z * q2 + p1.w * q3;
    ko.x = p0.x * k0 + p0.y * k1;  ko.y = p0.z * k0 + p0.w * k1;
    ko.z = p1.x * k2 + p1.y * k3;  ko.w = p1.z * k2 + p1.w * k3;

    size_t o = ((size_t)hd * SEQ + l) * HD + lane * 4;
    __nv_bfloat162 hA, hB, lA, lB;
    uint2 uh, ul;
    hA.x = __float2bfloat16(qo.x); hA.y = __float2bfloat16(qo.y);
    hB.x = __float2bfloat16(qo.z); hB.y = __float2bfloat16(qo.w);
    lA.x = __float2bfloat16(qo.x - __bfloat162float(hA.x));
    lA.y = __float2bfloat16(qo.y - __bfloat162float(hA.y));
    lB.x = __float2bfloat16(qo.z - __bfloat162float(hB.x));
    lB.y = __float2bfloat16(qo.w - __bfloat162float(hB.y));
    uh.x = *(uint32_t*)&hA; uh.y = *(uint32_t*)&hB;
    ul.x = *(uint32_t*)&lA; ul.y = *(uint32_t*)&lB;
    *(uint2*)(d_qh + o) = uh; *(uint2*)(d_ql + o) = ul;

    hA.x = __float2bfloat16(ko.x); hA.y = __float2bfloat16(ko.y);
    hB.x = __float2bfloat16(ko.z); hB.y = __float2bfloat16(ko.w);
    lA.x = __float2bfloat16(ko.x - __bfloat162float(hA.x));
    lA.y = __float2bfloat16(ko.y - __bfloat162float(hA.y));
    lB.x = __float2bfloat16(ko.z - __bfloat162float(hB.x));
    lB.y = __float2bfloat16(ko.w - __bfloat162float(hB.y));
    uh.x = *(uint32_t*)&hA; uh.y = *(uint32_t*)&hB;
    ul.x = *(uint32_t*)&lA; ul.y = *(uint32_t*)&lB;
    *(uint2*)(d_kh + o) = uh; *(uint2*)(d_kl + o) = ul;

    *reinterpret_cast<float4*>(d_v + o) = vv;
}

// row softmax over d_s; outputs split bf16 probs to d_sh/d_sl
__global__ void softmax_split_kernel() {
    size_t rowoff = (size_t)blockIdx.x * SEQ;
    float* row = d_s + rowoff;
    int tid = threadIdx.x;
    float v[8];
    float m = -1e30f;
#pragma unroll
    for (int j = 0; j < 8; j++) { v[j] = row[tid + j * 256]; m = fmaxf(m, v[j]); }
    __shared__ float red[256];
    red[tid] = m;
    __syncthreads();
    for (int o = 128; o > 0; o >>= 1) {
        if (tid < o) red[tid] = fmaxf(red[tid], red[tid + o]);
        __syncthreads();
    }
    m = red[0];
    __syncthreads();
    float s = 0.0f;
#pragma unroll
    for (int j = 0; j < 8; j++) { v[j] = __expf(v[j] - m); s += v[j]; }
    red[tid] = s;
    __syncthreads();
    for (int o = 128; o > 0; o >>= 1) {
        if (tid < o) red[tid] += red[tid + o];
        __syncthreads();
    }
    float inv = 1.0f / red[0];
#pragma unroll
    for (int j = 0; j < 8; j++) {
        float p = v[j] * inv;
        __nv_bfloat16 h = __float2bfloat16(p);
        d_sh[rowoff + tid + j * 256] = h;
        d_sl[rowoff + tid + j * 256] = __float2bfloat16(p - __bfloat162float(h));
    }
}

// gelu(mlp half of h) -> split bf16 directly into a2 [:, HIDDEN:]
__global__ void gelu_split_kernel() {
    size_t g = ((size_t)blockIdx.x * 256 + threadIdx.x) * 2;
    size_t r = g / MLPD;
    int j = (int)(g % MLPD);
    float2 xv = *(const float2*)(d_h + r * W1N + 3 * HIDDEN + j);
    float t0 = tanhf(0.7978845608028654f * (xv.x + 0.044715f * xv.x * xv.x * xv.x));
    float t1 = tanhf(0.7978845608028654f * (xv.y + 0.044715f * xv.y * xv.y * xv.y));
    float g0 = 0.5f * xv.x * (1.0f + t0);
    float g1 = 0.5f * xv.y * (1.0f + t1);
    __nv_bfloat162 hp, lp;
    hp.x = __float2bfloat16(g0); hp.y = __float2bfloat16(g1);
    lp.x = __float2bfloat16(g0 - __bfloat162float(hp.x));
    lp.y = __float2bfloat16(g1 - __bfloat162float(hp.y));
    size_t o = r * CATN + HIDDEN + j;
    *(uint32_t*)(d_a2h + o) = *(uint32_t*)&hp;
    *(uint32_t*)(d_a2l + o) = *(uint32_t*)&lp;
}

// =================== driver =================================================
extern "C" void kernel_launch(void* const* d_in, const int* in_sizes, int n_in,
                              void* d_out, int out_size) {
    const float* x     = (const float*)d_in[0];
    const float* vec   = (const float*)d_in[1];
    const float* pe    = (const float*)d_in[2];
    const float* w1    = (const float*)d_in[3];
    const float* b1    = (const float*)d_in[4];
    const float* w2    = (const float*)d_in[5];
    const float* b2    = (const float*)d_in[6];
    const float* mod_w = (const float*)d_in[7];
    const float* mod_b = (const float*)d_in[8];
    const float* qnw   = (const float*)d_in[9];
    const float* knw   = (const float*)d_in[10];
    float* out = (float*)d_out;

    float *p_mod, *p_xmod, *p_h, *p_s;
    __nv_bfloat16 *p_a1h, *p_a1l, *p_a2h, *p_a2l, *p_w1th, *p_w1tl, *p_w2th, *p_w2tl;
    __nv_bfloat16 *p_qh, *p_ql, *p_kh, *p_kl, *p_vth, *p_vtl, *p_sh, *p_sl;
    cudaGetSymbolAddress((void**)&p_mod,  d_mod);
    cudaGetSymbolAddress((void**)&p_xmod, d_xmod);
    cudaGetSymbolAddress((void**)&p_h,    d_h);
    cudaGetSymbolAddress((void**)&p_s,    d_s);
    cudaGetSymbolAddress((void**)&p_a1h,  d_a1h);
    cudaGetSymbolAddress((void**)&p_a1l,  d_a1l);
    cudaGetSymbolAddress((void**)&p_a2h,  d_a2h);
    cudaGetSymbolAddress((void**)&p_a2l,  d_a2l);
    cudaGetSymbolAddress((void**)&p_w1th, d_w1th);
    cudaGetSymbolAddress((void**)&p_w1tl, d_w1tl);
    cudaGetSymbolAddress((void**)&p_w2th, d_w2th);
    cudaGetSymbolAddress((void**)&p_w2tl, d_w2tl);
    cudaGetSymbolAddress((void**)&p_qh,   d_qh);
    cudaGetSymbolAddress((void**)&p_ql,   d_ql);
    cudaGetSymbolAddress((void**)&p_kh,   d_kh);
    cudaGetSymbolAddress((void**)&p_kl,   d_kl);
    cudaGetSymbolAddress((void**)&p_vth,  d_vth);
    cudaGetSymbolAddress((void**)&p_vtl,  d_vtl);
    cudaGetSymbolAddress((void**)&p_sh,   d_sh);
    cudaGetSymbolAddress((void**)&p_sl,   d_sl);

    cudaFuncSetAttribute(hmma_gemm_kernel, cudaFuncAttributeMaxDynamicSharedMemorySize,
                         HMMA_SMEM_BYTES);

    // lazily-created side stream + events (created during correctness run,
    // reused during capture; creation is host-side only, no device memory)
    static cudaStream_t sB = nullptr;
    static cudaEvent_t evW1, evSplit, evQP, evG2a;
    if (!sB) {
        cudaStreamCreateWithFlags(&sB, cudaStreamNonBlocking);
        cudaEventCreateWithFlags(&evW1,    cudaEventDisableTiming);
        cudaEventCreateWithFlags(&evSplit, cudaEventDisableTiming);
        cudaEventCreateWithFlags(&evQP,    cudaEventDisableTiming);
        cudaEventCreateWithFlags(&evG2a,   cudaEventDisableTiming);
    }

    const float sc = 0.08838834764831845f;
    const long long Z = 0;

    // ---- fork stream B off the capture (legacy) stream -----------------
    static cudaEvent_t evFork = nullptr;
    if (!evFork) cudaEventCreateWithFlags(&evFork, cudaEventDisableTiming);
    cudaEventRecord(evFork, 0);
    cudaStreamWaitEvent(sB, evFork, 0);

    // ---- stream B: weight transposes ----------------------------------
    transpose_split_kernel<<<dim3(W1N / 32, HIDDEN / 32), dim3(32, 8), 0, sB>>>(
        w1, HIDDEN, W1N, p_w1th, p_w1tl);
    cudaEventRecord(evW1, sB);
    transpose_split_kernel<<<dim3(HIDDEN / 32, CATN / 32), dim3(32, 8), 0, sB>>>(
        w2, CATN, HIDDEN, p_w2th, p_w2tl);

    // ---- stream A (legacy): activations prep --------------------------
    mod_gemv_kernel<<<MODN / 256, 256>>>(vec, mod_w, mod_b, p_mod);
    ln_mod_kernel<<<SEQ, 256>>>(x);
    split_kernel<<<(SEQ * HIDDEN) / 1024, 256>>>(p_xmod, p_a1h, p_a1l);
    cudaEventRecord(evSplit, 0);

    // A: GEMM1 qkv columns (needs w1t)
    cudaStreamWaitEvent(0, evW1, 0);
    hmma_gemm_kernel<<<dim3(SEQ / 128, (3 * HIDDEN) / 128, 1), 256, HMMA_SMEM_BYTES>>>(
        p_a1h, p_a1l, HIDDEN, Z, p_w1th, p_w1tl, HIDDEN, Z, p_h, W1N, Z,
        HIDDEN, 1.0f, 1, b1, nullptr, nullptr, nullptr, nullptr, nullptr);

    // B: GEMM1 mlp columns (needs split + w1t; both via evSplit + same-stream w1t)
    cudaStreamWaitEvent(sB, evSplit, 0);
    hmma_gemm_kernel<<<dim3(SEQ / 128, MLPD / 128, 1), 256, HMMA_SMEM_BYTES, sB>>>(
        p_a1h, p_a1l, HIDDEN, Z, p_w1th + (size_t)(3 * HIDDEN) * HIDDEN,
        p_w1tl + (size_t)(3 * HIDDEN) * HIDDEN, HIDDEN, Z,
        p_h + 3 * HIDDEN, W1N, Z,
        HIDDEN, 1.0f, 1, b1 + 3 * HIDDEN, nullptr, nullptr, nullptr, nullptr, nullptr);
    // B: gelu -> a2 mlp cols, then GEMM2a (mlp K-slice) -> partial in d_xmod
    gelu_split_kernel<<<(SEQ * MLPD) / 512, 256, 0, sB>>>();
    hmma_gemm_kernel<<<dim3(SEQ / 128, HIDDEN / 128, 1), 256, HMMA_SMEM_BYTES, sB>>>(
        p_a2h + HIDDEN, p_a2l + HIDDEN, CATN, Z,
        p_w2th + HIDDEN, p_w2tl + HIDDEN, CATN, Z,
        p_xmod, HIDDEN, Z,
        MLPD, 1.0f, 0, nullptr, nullptr, nullptr, nullptr, nullptr, nullptr);
    cudaEventRecord(evG2a, sB);

    // ---- stream A: attention chain -------------------------------------
    qkv_prep_kernel<<<SEQ * NH / 8, 256>>>(pe, qnw, knw);
    transpose_split_v_kernel<<<dim3(HD / 32, SEQ / 32, NH), dim3(32, 8)>>>();
    hmma_gemm_kernel<<<dim3(SEQ / 128, SEQ / 128, NH), 256, HMMA_SMEM_BYTES>>>(
        p_qh, p_ql, HD, (long long)SEQ * HD, p_kh, p_kl, HD, (long long)SEQ * HD,
        p_s, SEQ, (long long)SEQ * SEQ,
        HD, sc, 0, nullptr, nullptr, nullptr, nullptr, nullptr, nullptr);
    softmax_split_kernel<<<NH * SEQ, 256>>>();
    hmma_gemm_kernel<<<dim3(SEQ / 128, 1, NH), 256, HMMA_SMEM_BYTES>>>(
        p_sh, p_sl, SEQ, (long long)SEQ * SEQ, p_vth, p_vtl, SEQ, (long long)HD * SEQ,
        nullptr, CATN, (long long)HD,
        SEQ, 1.0f, 3, nullptr, nullptr, nullptr, p_a2h, p_a2l, nullptr);

    // ---- join: GEMM2b (attention K-slice) + full epilogue ---------------
    cudaStreamWaitEvent(0, evG2a, 0);
    hmma_gemm_kernel<<<dim3(SEQ / 128, HIDDEN / 128, 1), 256, HMMA_SMEM_BYTES>>>(
        p_a2h, p_a2l, CATN, Z, p_w2th, p_w2tl, CATN, Z, out, HIDDEN, Z,
        HIDDEN, 1.0f, 4, b2, x, p_mod + 2 * HIDDEN, nullptr, nullptr, p_xmod);
}